// round 8
// baseline (speedup 1.0000x reference)
#include <cuda_runtime.h>
#include <math.h>

// Problem constants (fixed instance)
#define BB 2
#define NN 2048
#define FEMB 16
#define FFEAT 2
#define FIN 18
#define EE 64
#define HH 2
#define KK 2
#define HID 64
#define BN (BB*NN)

// ---------------- scratch (static device globals; no runtime allocation) ----------------
__device__ float g_h[BN*EE];                 // node hidden state
__device__ float g_z[HH*BN*EE];              // per-head projected features
__device__ float g_ssrc[HH*BN];
__device__ float g_sdst[HH*BN];
__device__ float g_zmean[HH*BB*EE];          // fallback for empty neighbor rows
__device__ float g_aggp[HH*BN*KK*EE];        // per-head aggregation partials
__device__ int   g_rowptr[KK*BN];
__device__ int   g_deg[KK*BN];
__device__ int   g_col[KK*BN*NN];            // CSR col indices, fixed row*NN bases
__device__ float g_nw[BN];                   // decoder node weights
__device__ float g_dv[BN];                   // dual vars
__device__ float g_eprop[BN*NN];             // per-edge prop value (k=0 edge index space)
__device__ int   g_erecip[BN*NN];            // reciprocal edge index or -1
__device__ int   g_indeg[BN];
__device__ int   g_cscPtr[BN+1];
__device__ int   g_cscFill[BN];
__device__ int   g_cscSrc[BN*NN];            // src global row per in-edge
__device__ int   g_cscEdge[BN*NN];           // edge index per in-edge

// ---------------------------------------------------------------------------------------
__global__ void k_init() {
    int i = blockIdx.x * blockDim.x + threadIdx.x;
    if (i < BN) { g_indeg[i] = 0; g_cscFill[i] = 0; }
    if (i < HH*BB*EE) g_zmean[i] = 0.f;
}

// encoder: h = tanh(tanh([emb,feat]@W0+b0)@W1+b1), one block (64 thr) per node
__global__ void k_encoder(const float* __restrict__ emb, const float* __restrict__ feat,
                          const float* __restrict__ W0, const float* __restrict__ b0,
                          const float* __restrict__ W1, const float* __restrict__ b1) {
    int node = blockIdx.x;
    int e = threadIdx.x;
    __shared__ float x[FIN];
    __shared__ float h0[HID];
    if (e < FEMB) x[e] = emb[node*FEMB + e];
    else if (e < FIN) x[e] = feat[node*FFEAT + (e - FEMB)];
    __syncthreads();
    float acc = b0[e];
#pragma unroll
    for (int f = 0; f < FIN; f++) acc = fmaf(x[f], W0[f*HID + e], acc);
    h0[e] = tanhf(acc);
    __syncthreads();
    float a0 = b1[e], a1 = 0.f;
#pragma unroll 8
    for (int f = 0; f < HID; f += 2) {
        a0 = fmaf(h0[f],     W1[f*EE + e],       a0);
        a1 = fmaf(h0[f + 1], W1[(f + 1)*EE + e], a1);
    }
    g_h[node*EE + e] = tanhf(a0 + a1);
}

// CSR build: single pass, fixed row bases (no compaction across rows, no atomics).
// one warp per (k,b,n) row; 4 pre-batched loads per loop for MLP.
__global__ void k_build_csr(const float* __restrict__ nbh) {
    int wrow = blockIdx.x * (blockDim.x >> 5) + (threadIdx.x >> 5);
    int lane = threadIdx.x & 31;
    if (wrow >= KK*BN) return;
    const float* row = nbh + (size_t)wrow * NN;
    int rbase = wrow * NN;
    unsigned lt = (1u << lane) - 1u;
    int off = 0;
#pragma unroll 4
    for (int j0 = 0; j0 < NN; j0 += 128) {
        float v0 = row[j0 + lane];
        float v1 = row[j0 + 32 + lane];
        float v2 = row[j0 + 64 + lane];
        float v3 = row[j0 + 96 + lane];
        unsigned b0 = __ballot_sync(0xffffffffu, v0 > 0.f);
        if (v0 > 0.f) g_col[rbase + off + __popc(b0 & lt)] = j0 + lane;
        off += __popc(b0);
        unsigned b1 = __ballot_sync(0xffffffffu, v1 > 0.f);
        if (v1 > 0.f) g_col[rbase + off + __popc(b1 & lt)] = j0 + 32 + lane;
        off += __popc(b1);
        unsigned b2 = __ballot_sync(0xffffffffu, v2 > 0.f);
        if (v2 > 0.f) g_col[rbase + off + __popc(b2 & lt)] = j0 + 64 + lane;
        off += __popc(b2);
        unsigned b3 = __ballot_sync(0xffffffffu, v3 > 0.f);
        if (v3 > 0.f) g_col[rbase + off + __popc(b3 & lt)] = j0 + 96 + lane;
        off += __popc(b3);
    }
    if (lane == 0) { g_rowptr[wrow] = rbase; g_deg[wrow] = off; }
}

// reciprocal edge index (binary search; cols ascending) + in-degree count, fused.
__global__ void k_recip_indeg() {
    int warp = blockIdx.x * (blockDim.x >> 5) + (threadIdx.x >> 5);
    int lane = threadIdx.x & 31;
    if (warp >= BN) return;
    int b = warp / NN;
    int n = warp - b*NN;
    int rbase = g_rowptr[warp];
    int deg = g_deg[warp];
    for (int idx = lane; idx < deg; idx += 32) {
        int j = g_col[rbase + idx];
        int jr = b*NN + j;
        int jb = g_rowptr[jr], dj = g_deg[jr];
        int lo = 0, hi = dj;
        while (lo < hi) { int mid = (lo + hi) >> 1; if (g_col[jb + mid] < n) lo = mid + 1; else hi = mid; }
        g_erecip[rbase + idx] = (lo < dj && g_col[jb + lo] == n) ? (jb + lo) : -1;
        atomicAdd(&g_indeg[jr], 1);
    }
}

// exclusive scan of indeg (single block, 1024 threads x 4 elems)
__global__ void k_scan() {
    __shared__ int ssum[1024];
    int t = threadIdx.x;
    int base = t * 4;
    int v[4];
    int s = 0;
#pragma unroll
    for (int i = 0; i < 4; i++) { v[i] = s; s += g_indeg[base + i]; }
    ssum[t] = s; __syncthreads();
    for (int off = 1; off < 1024; off <<= 1) {
        int x = (t >= off) ? ssum[t - off] : 0;
        __syncthreads();
        ssum[t] += x;
        __syncthreads();
    }
    int pre = (t == 0) ? 0 : ssum[t - 1];
#pragma unroll
    for (int i = 0; i < 4; i++) g_cscPtr[base + i] = pre + v[i];
    if (t == 1023) g_cscPtr[BN] = ssum[1023];
}

__global__ void k_cscfill() {
    int warp = blockIdx.x * (blockDim.x >> 5) + (threadIdx.x >> 5);
    int lane = threadIdx.x & 31;
    if (warp >= BN) return;
    int b = warp / NN;
    int rbase = g_rowptr[warp];
    int deg = g_deg[warp];
    for (int idx = lane; idx < deg; idx += 32) {
        int dst = b*NN + g_col[rbase + idx];
        int pos = g_cscPtr[dst] + atomicAdd(&g_cscFill[dst], 1);
        g_cscSrc[pos] = warp;
        g_cscEdge[pos] = rbase + idx;
    }
}

// z = h @ attn_W per head; s_src/s_dst row scores. block (128 thr) per node.
__global__ void k_z(const float* __restrict__ attn_W, const float* __restrict__ a_src,
                    const float* __restrict__ a_dst) {
    int node = blockIdx.x;
    int t = threadIdx.x;
    int head = t >> 6, e = t & 63;
    __shared__ float hs[EE];
    __shared__ float rs[2], rd[2];
    if (t < EE) hs[t] = g_h[node*EE + t];
    if (t < 2) { rs[t] = 0.f; rd[t] = 0.f; }
    __syncthreads();
    const float* W = attn_W + head*EE*EE;
    float a0 = 0.f, a1 = 0.f, a2 = 0.f, a3 = 0.f;
#pragma unroll 4
    for (int d = 0; d < EE; d += 4) {
        a0 = fmaf(hs[d],     W[d*EE + e],       a0);
        a1 = fmaf(hs[d + 1], W[(d + 1)*EE + e], a1);
        a2 = fmaf(hs[d + 2], W[(d + 2)*EE + e], a2);
        a3 = fmaf(hs[d + 3], W[(d + 3)*EE + e], a3);
    }
    float acc = (a0 + a1) + (a2 + a3);
    g_z[((size_t)head*BN + node)*EE + e] = acc;
    float vs = acc * a_src[head*EE + e];
    float vd = acc * a_dst[head*EE + e];
#pragma unroll
    for (int o = 16; o > 0; o >>= 1) {
        vs += __shfl_xor_sync(0xffffffffu, vs, o);
        vd += __shfl_xor_sync(0xffffffffu, vd, o);
    }
    if ((t & 31) == 0) { atomicAdd(&rs[head], vs); atomicAdd(&rd[head], vd); }
    __syncthreads();
    if (t < 2) { g_ssrc[t*BN + node] = rs[t]; g_sdst[t*BN + node] = rd[t]; }
}

// column means of z (fallback for degree-0 rows). grid = HH*BB*16, block 64.
__global__ void k_zmean_acc() {
    int hb = blockIdx.x >> 4;
    int c = blockIdx.x & 15;
    int e = threadIdx.x;
    float acc = 0.f;
    for (int n = c*128; n < c*128 + 128; n++)
        acc += g_z[((size_t)hb*NN + n)*EE + e];
    atomicAdd(&g_zmean[hb*EE + e], acc * (1.0f / NN));
}

// sparse attention aggregation: one warp per (head,k,node). float2 loads, per-head partials.
__global__ void k_agg() {
    int warp = blockIdx.x * (blockDim.x >> 5) + (threadIdx.x >> 5);
    int lane = threadIdx.x & 31;
    if (warp >= HH*KK*BN) return;
    int head = warp / (KK*BN);
    int rem = warp - head*(KK*BN);
    int k = rem / BN;
    int node = rem - k*BN;
    int b = node / NN;
    float ss = g_ssrc[head*BN + node];
    const float* sd = g_sdst + head*BN + b*NN;
    const float2* z = (const float2*)(g_z + ((size_t)head*BN + (size_t)b*NN)*EE);
    int crow = k*BN + node;
    int rbase = g_rowptr[crow];
    int deg = g_deg[crow];
    float accx = 0.f, accy = 0.f, Z = 0.f;
    for (int i0 = 0; i0 < deg; i0 += 32) {
        int idx = i0 + lane;
        int m = (idx < deg) ? __ldg(&g_col[rbase + idx]) : -1;
        float w = (m >= 0) ? expf(tanhf(ss + sd[m])) : 0.f;
        float r = w;
#pragma unroll
        for (int o = 16; o > 0; o >>= 1) r += __shfl_xor_sync(0xffffffffu, r, o);
        Z += r;
        int cnt = deg - i0; if (cnt > 32) cnt = 32;
#pragma unroll 4
        for (int j = 0; j < cnt; j++) {
            int   mj = __shfl_sync(0xffffffffu, m, j);
            float wj = __shfl_sync(0xffffffffu, w, j);
            float2 v = __ldg(&z[mj*32 + lane]);
            accx = fmaf(wj, v.x, accx);
            accy = fmaf(wj, v.y, accy);
        }
    }
    float2 outv;
    if (deg > 0) {
        float inv = 1.f / Z;
        outv.x = accx * inv; outv.y = accy * inv;
    } else {
        outv.x = g_zmean[(head*BB + b)*EE + 2*lane];
        outv.y = g_zmean[(head*BB + b)*EE + 2*lane + 1];
    }
    float2* dst = (float2*)(g_aggp + (((size_t)head*BN + node)*KK + k)*EE);
    dst[lane] = outv;
}

// combine heads + neighborhood attention over k + GRU update. block (64 thr) per node.
// also re-zeroes g_zmean (block 0) for the next layer.
__global__ void k_update(const float* __restrict__ nbr_q, const float* __restrict__ gru_W,
                         const float* __restrict__ gru_U, const float* __restrict__ gru_b) {
    int node = blockIdx.x;
    int e = threadIdx.x;
    __shared__ float a0[EE], a1[EE], hs[EE], nxt[EE], rh[EE];
    __shared__ float red[2];
    size_t i00 = (((size_t)0*BN + node)*KK + 0)*EE + e;
    size_t i01 = (((size_t)0*BN + node)*KK + 1)*EE + e;
    size_t i10 = (((size_t)1*BN + node)*KK + 0)*EE + e;
    size_t i11 = (((size_t)1*BN + node)*KK + 1)*EE + e;
    a0[e] = tanhf(0.5f*(g_aggp[i00] + g_aggp[i10]));
    a1[e] = tanhf(0.5f*(g_aggp[i01] + g_aggp[i11]));
    hs[e] = g_h[node*EE + e];
    if (e < 2) red[e] = 0.f;
    if (node == 0) {
        g_zmean[e] = 0.f; g_zmean[64 + e] = 0.f;
        g_zmean[128 + e] = 0.f; g_zmean[192 + e] = 0.f;
    }
    __syncthreads();
    float q = nbr_q[e];
    float v0 = a0[e]*q, v1 = a1[e]*q;
#pragma unroll
    for (int o = 16; o > 0; o >>= 1) {
        v0 += __shfl_xor_sync(0xffffffffu, v0, o);
        v1 += __shfl_xor_sync(0xffffffffu, v1, o);
    }
    if ((e & 31) == 0) { atomicAdd(&red[0], v0); atomicAdd(&red[1], v1); }
    __syncthreads();
    float t0 = tanhf(red[0]), t1 = tanhf(red[1]);
    float e0 = expf(t0), e1 = expf(t1);
    float inv = 1.f / (e0 + e1);
    nxt[e] = e0*inv*a0[e] + e1*inv*a1[e];
    __syncthreads();
    float sW0 = 0.f, sW1 = 0.f, sW2 = 0.f, sU0 = 0.f, sU1 = 0.f;
#pragma unroll 8
    for (int d = 0; d < EE; d++) {
        float nd = nxt[d], hd = hs[d];
        const float* Wr = gru_W + d*192;
        const float* Ur = gru_U + d*192;
        sW0 = fmaf(nd, Wr[e],       sW0);
        sW1 = fmaf(nd, Wr[e + 64],  sW1);
        sW2 = fmaf(nd, Wr[e + 128], sW2);
        sU0 = fmaf(hd, Ur[e],       sU0);
        sU1 = fmaf(hd, Ur[e + 64],  sU1);
    }
    float zg = 1.f / (1.f + expf(-(sW0 + sU0 + gru_b[e])));
    float r  = 1.f / (1.f + expf(-(sW1 + sU1 + gru_b[e + 64])));
    rh[e] = r * hs[e];
    __syncthreads();
    float sU2 = 0.f;
#pragma unroll 8
    for (int d = 0; d < EE; d++) sU2 = fmaf(rh[d], gru_U[d*192 + e + 128], sU2);
    float htl = tanhf(sW2 + sU2 + gru_b[e + 128]);
    g_h[node*EE + e] = (1.f - zg)*hs[e] + zg*htl;
}

// decoder + dual-var MLPs fused. block (64 thr) per node.
__global__ void k_decode(const float* __restrict__ dW0, const float* __restrict__ db0,
                         const float* __restrict__ dW1, const float* __restrict__ db1,
                         const float* __restrict__ uW0, const float* __restrict__ ub0,
                         const float* __restrict__ uW1, const float* __restrict__ ub1) {
    int node = blockIdx.x;
    int e = threadIdx.x;
    __shared__ float hs[EE];
    __shared__ float red[2];
    hs[e] = g_h[node*EE + e];
    if (e < 2) red[e] = 0.f;
    __syncthreads();
    float ad = db0[e], au = ub0[e];
#pragma unroll 8
    for (int d = 0; d < EE; d++) {
        float hd = hs[d];
        ad = fmaf(hd, dW0[d*64 + e], ad);
        au = fmaf(hd, uW0[d*64 + e], au);
    }
    float vd = tanhf(ad) * dW1[e];
    float vu = tanhf(au) * uW1[e];
#pragma unroll
    for (int o = 16; o > 0; o >>= 1) {
        vd += __shfl_xor_sync(0xffffffffu, vd, o);
        vu += __shfl_xor_sync(0xffffffffu, vu, o);
    }
    if ((e & 31) == 0) { atomicAdd(&red[0], vd); atomicAdd(&red[1], vu); }
    __syncthreads();
    if (e == 0) { g_nw[node] = red[0] + db1[0]; g_dv[node] = red[1] + ub1[0]; }
}

// ===== mega-fused flow + dual section: one CTA per batch =====
// eprop softmax -> s-init -> 9 sparse matvec iters (s in SMEM) -> cost + dual + final.
__global__ void __launch_bounds__(1024) k_flow(const float* __restrict__ demands,
                                               float* __restrict__ out) {
    int b = blockIdx.x;
    int t = threadIdx.x;
    int warp = t >> 5, lane = t & 31;
    __shared__ float ss0[NN], ss1[NN];
    __shared__ float s_empty, s_emptyNext;
    __shared__ double redf[32], redd[32], reddd[32];

    const float* nwb = g_nw + b*NN;

    // ---- per-edge prop (row softmax over neighbors): warp per row ----
    for (int r = warp; r < NN; r += 32) {
        int row = b*NN + r;
        int rbase = g_rowptr[row];
        int deg = g_deg[row];
        if (deg == 0) continue;
        float mx = -3.0e38f;
        for (int i = lane; i < deg; i += 32) mx = fmaxf(mx, nwb[g_col[rbase + i]]);
#pragma unroll
        for (int o = 16; o > 0; o >>= 1) mx = fmaxf(mx, __shfl_xor_sync(0xffffffffu, mx, o));
        float sm = 0.f;
        for (int i = lane; i < deg; i += 32) sm += expf(nwb[g_col[rbase + i]] - mx);
#pragma unroll
        for (int o = 16; o > 0; o >>= 1) sm += __shfl_xor_sync(0xffffffffu, sm, o);
        float inv = 1.f / sm;
        for (int i = lane; i < deg; i += 32)
            g_eprop[rbase + i] = expf(nwb[g_col[rbase + i]] - mx) * inv;
    }

    // ---- s0 = relu(-d); seed uniform mass ----
    if (t == 0) { s_empty = 0.f; s_emptyNext = 0.f; }
    __syncthreads();
    {
        float em = 0.f;
        for (int n = t; n < NN; n += 1024) {
            float v = fmaxf(-demands[b*NN + n], 0.f);
            ss0[n] = v;
            if (g_deg[b*NN + n] == 0) em += v;
        }
        if (em != 0.f) atomicAdd(&s_empty, em);
    }
    __syncthreads();

    // ---- 9 sparse matvec iterations, s in shared memory ----
    float* scur = ss0;
    float* snxt = ss1;
    for (int it = 0; it < 9; it++) {
        float uni = s_empty * (1.0f / NN);
        float emn = 0.f;
        for (int n = t; n < NN; n += 1024) {
            int g = b*NN + n;
            int p0 = g_cscPtr[g], p1 = g_cscPtr[g + 1];
            float acc = 0.f;
            for (int q = p0; q < p1; q++)
                acc += g_eprop[g_cscEdge[q]] * scur[g_cscSrc[q] - b*NN];
            float sv = fmaxf(acc + uni - demands[g], 0.f);
            snxt[n] = sv;
            if (g_deg[g] == 0) emn += sv;
        }
        if (emn != 0.f) atomicAdd(&s_emptyNext, emn);
        __syncthreads();
        if (t == 0) { s_empty = s_emptyNext; s_emptyNext = 0.f; }
        float* tmp = scur; scur = snxt; snxt = tmp;
        __syncthreads();
    }
    // scur holds final s

    // ---- fused flow-cost + dual-edge-cost: warp per row over out-edges ----
    float facc = 0.f, dacc = 0.f;
    for (int r = warp; r < NN; r += 32) {
        int row = b*NN + r;
        int rbase = g_rowptr[row];
        int deg = g_deg[row];
        float si = scur[r];
        float dvi = g_dv[row];
        for (int idx = lane; idx < deg; idx += 32) {
            int e = rbase + idx;
            int j = g_col[e];
            float f = g_eprop[e] * si;
            int rc = g_erecip[e];
            float frec = (rc >= 0) ? g_eprop[rc] * scur[j]
                                   : ((g_deg[b*NN + j] == 0) ? scur[j] * (1.0f / NN) : 0.f);
            float fl = f - fminf(f, frec);
            facc = fmaf(fl, fl, facc);
            float dd = dvi - g_dv[b*NN + j];
            float y = 0.f, m = 0.f;
#pragma unroll
            for (int itr = 0; itr < 10; itr++) {
                float g2 = 2.f*y - dd;
                m = 0.9f*m + g2;
                y = fmaxf(y - 0.1f*m, 0.f);
            }
            dacc += y*y - dd*y;
        }
        if (deg == 0 && lane == 0) facc += si * si * (1.0f / NN);
    }
    double ddem = 0.0;
    for (int n = t; n < NN; n += 1024)
        ddem += (double)(g_dv[b*NN + n] * demands[b*NN + n]);

    // block reduce (double)
    double df = (double)facc, dd2 = (double)dacc;
#pragma unroll
    for (int o = 16; o > 0; o >>= 1) {
        df   += __shfl_xor_sync(0xffffffffu, df, o);
        dd2  += __shfl_xor_sync(0xffffffffu, dd2, o);
        ddem += __shfl_xor_sync(0xffffffffu, ddem, o);
    }
    if (lane == 0) { redf[warp] = df; redd[warp] = dd2; reddd[warp] = ddem; }
    __syncthreads();
    if (warp == 0) {
        double a = redf[lane], c = redd[lane], d = reddd[lane];
#pragma unroll
        for (int o = 16; o > 0; o >>= 1) {
            a += __shfl_xor_sync(0xffffffffu, a, o);
            c += __shfl_xor_sync(0xffffffffu, c, o);
            d += __shfl_xor_sync(0xffffffffu, d, o);
        }
        if (lane == 0) out[b] = (float)(a - (c - d));
    }
}

// ---------------------------------------------------------------------------------------
extern "C" void kernel_launch(void* const* d_in, const int* in_sizes, int n_in,
                              void* d_out, int out_size) {
    const float* node_features   = (const float*)d_in[0];
    const float* node_embeddings = (const float*)d_in[1];
    const float* demands = (const float*)d_in[2];
    const float* nbh     = (const float*)d_in[4];
    const float* enc_W0  = (const float*)d_in[5];
    const float* enc_b0  = (const float*)d_in[6];
    const float* enc_W1  = (const float*)d_in[7];
    const float* enc_b1  = (const float*)d_in[8];
    const float* attn_W  = (const float*)d_in[9];
    const float* a_src   = (const float*)d_in[10];
    const float* a_dst   = (const float*)d_in[11];
    const float* nbr_q   = (const float*)d_in[12];
    const float* gru_W   = (const float*)d_in[13];
    const float* gru_U   = (const float*)d_in[14];
    const float* gru_b   = (const float*)d_in[15];
    const float* dec_W0  = (const float*)d_in[16];
    const float* dec_b0  = (const float*)d_in[17];
    const float* dec_W1  = (const float*)d_in[18];
    const float* dec_b1  = (const float*)d_in[19];
    const float* dual_W0 = (const float*)d_in[20];
    const float* dual_b0 = (const float*)d_in[21];
    const float* dual_W1 = (const float*)d_in[22];
    const float* dual_b1 = (const float*)d_in[23];
    float* out = (float*)d_out;

    k_init<<<(BN + 255)/256, 256>>>();
    k_encoder<<<BN, 64>>>(node_embeddings, node_features, enc_W0, enc_b0, enc_W1, enc_b1);
    k_build_csr<<<(KK*BN)/8, 256>>>(nbh);
    k_recip_indeg<<<BN/8, 256>>>();
    k_scan<<<1, 1024>>>();
    k_cscfill<<<BN/8, 256>>>();

    for (int layer = 0; layer < 2; layer++) {
        k_z<<<BN, 128>>>(attn_W, a_src, a_dst);
        k_zmean_acc<<<HH*BB*16, 64>>>();
        k_agg<<<(HH*KK*BN)/8, 256>>>();
        k_update<<<BN, 64>>>(nbr_q, gru_W, gru_U, gru_b);
    }

    k_decode<<<BN, 64>>>(dec_W0, dec_b0, dec_W1, dec_b1, dual_W0, dual_b0, dual_W1, dual_b1);
    k_flow<<<BB, 1024>>>(demands, out);
}

// round 13
// speedup vs baseline: 1.9026x; 1.9026x over previous
#include <cuda_runtime.h>
#include <cuda_bf16.h>
#include <math.h>

// Problem constants (fixed instance)
#define BB 2
#define NN 2048
#define FEMB 16
#define FFEAT 2
#define FIN 18
#define EE 64
#define HH 2
#define KK 2
#define HID 64
#define BN (BB*NN)

// ---------------- scratch (static device globals; no runtime allocation) ----------------
__device__ float g_h[BN*EE];                 // node hidden state
__device__ float g_z[HH*BN*EE];              // per-head projected features (fp32, for zmean)
__device__ __align__(16) __nv_bfloat16 g_zb[HH*BN*EE];  // bf16 copy for gather traffic
__device__ float g_ssrc[HH*BN];
__device__ float g_sdst[HH*BN];
__device__ float g_zmean[HH*BB*EE];          // fallback for empty neighbor rows
__device__ float g_aggp[HH*BN*KK*EE];        // per-head aggregation partials
__device__ int   g_rowptr[KK*BN];
__device__ int   g_deg[KK*BN];
__device__ int   g_col[KK*BN*NN];            // CSR col indices, fixed row*NN bases
__device__ float g_nw[BN];                   // decoder node weights
__device__ float g_dv[BN];                   // dual vars
__device__ float g_eprop[BN*NN];             // per-edge prop value (k=0 edge index space)
__device__ int   g_erecip[BN*NN];            // reciprocal edge index or -1
__device__ int   g_indeg[BN];
__device__ int   g_cscPtr[BN+1];
__device__ int   g_cscFill[BN];
__device__ int   g_cscSrc[BN*NN];            // src global row per in-edge
__device__ int   g_cscEdge[BN*NN];           // edge index per in-edge
__device__ float g_s0[BN], g_s1[BN];         // flow scalar ping-pong
__device__ float g_emptyArr[10*BB];          // uniform-mass scalar per iteration input
__device__ double g_accflow[BB], g_accdual[BB];

// ---------------------------------------------------------------------------------------
__global__ void k_init() {
    int i = blockIdx.x * blockDim.x + threadIdx.x;
    if (i < BN) { g_indeg[i] = 0; g_cscFill[i] = 0; }
    if (i < HH*BB*EE) g_zmean[i] = 0.f;
    if (i < 10*BB) g_emptyArr[i] = 0.f;
    if (i < BB) { g_accflow[i] = 0.0; g_accdual[i] = 0.0; }
}

// encoder: h = tanh(tanh([emb,feat]@W0+b0)@W1+b1), one block (64 thr) per node
__global__ void k_encoder(const float* __restrict__ emb, const float* __restrict__ feat,
                          const float* __restrict__ W0, const float* __restrict__ b0,
                          const float* __restrict__ W1, const float* __restrict__ b1) {
    int node = blockIdx.x;
    int e = threadIdx.x;
    __shared__ float x[FIN];
    __shared__ float h0[HID];
    if (e < FEMB) x[e] = emb[node*FEMB + e];
    else if (e < FIN) x[e] = feat[node*FFEAT + (e - FEMB)];
    __syncthreads();
    float acc = b0[e];
#pragma unroll
    for (int f = 0; f < FIN; f++) acc = fmaf(x[f], W0[f*HID + e], acc);
    h0[e] = tanhf(acc);
    __syncthreads();
    float a0 = b1[e], a1 = 0.f;
#pragma unroll 8
    for (int f = 0; f < HID; f += 2) {
        a0 = fmaf(h0[f],     W1[f*EE + e],       a0);
        a1 = fmaf(h0[f + 1], W1[(f + 1)*EE + e], a1);
    }
    g_h[node*EE + e] = tanhf(a0 + a1);
}

// CSR build: single pass, fixed row bases (no compaction across rows, no atomics).
__global__ void k_build_csr(const float* __restrict__ nbh) {
    int wrow = blockIdx.x * (blockDim.x >> 5) + (threadIdx.x >> 5);
    int lane = threadIdx.x & 31;
    if (wrow >= KK*BN) return;
    const float* row = nbh + (size_t)wrow * NN;
    int rbase = wrow * NN;
    unsigned lt = (1u << lane) - 1u;
    int off = 0;
#pragma unroll 4
    for (int j0 = 0; j0 < NN; j0 += 128) {
        float v0 = row[j0 + lane];
        float v1 = row[j0 + 32 + lane];
        float v2 = row[j0 + 64 + lane];
        float v3 = row[j0 + 96 + lane];
        unsigned b0 = __ballot_sync(0xffffffffu, v0 > 0.f);
        if (v0 > 0.f) g_col[rbase + off + __popc(b0 & lt)] = j0 + lane;
        off += __popc(b0);
        unsigned b1 = __ballot_sync(0xffffffffu, v1 > 0.f);
        if (v1 > 0.f) g_col[rbase + off + __popc(b1 & lt)] = j0 + 32 + lane;
        off += __popc(b1);
        unsigned b2 = __ballot_sync(0xffffffffu, v2 > 0.f);
        if (v2 > 0.f) g_col[rbase + off + __popc(b2 & lt)] = j0 + 64 + lane;
        off += __popc(b2);
        unsigned b3 = __ballot_sync(0xffffffffu, v3 > 0.f);
        if (v3 > 0.f) g_col[rbase + off + __popc(b3 & lt)] = j0 + 96 + lane;
        off += __popc(b3);
    }
    if (lane == 0) { g_rowptr[wrow] = rbase; g_deg[wrow] = off; }
}

// reciprocal edge index (binary search; cols ascending) + in-degree count, fused.
__global__ void k_recip_indeg() {
    int warp = blockIdx.x * (blockDim.x >> 5) + (threadIdx.x >> 5);
    int lane = threadIdx.x & 31;
    if (warp >= BN) return;
    int b = warp / NN;
    int n = warp - b*NN;
    int rbase = g_rowptr[warp];
    int deg = g_deg[warp];
    for (int idx = lane; idx < deg; idx += 32) {
        int j = g_col[rbase + idx];
        int jr = b*NN + j;
        int jb = g_rowptr[jr], dj = g_deg[jr];
        int lo = 0, hi = dj;
        while (lo < hi) { int mid = (lo + hi) >> 1; if (g_col[jb + mid] < n) lo = mid + 1; else hi = mid; }
        g_erecip[rbase + idx] = (lo < dj && g_col[jb + lo] == n) ? (jb + lo) : -1;
        atomicAdd(&g_indeg[jr], 1);
    }
}

// exclusive scan of indeg (single block, 1024 threads x 4 elems)
__global__ void k_scan() {
    __shared__ int ssum[1024];
    int t = threadIdx.x;
    int base = t * 4;
    int v[4];
    int s = 0;
#pragma unroll
    for (int i = 0; i < 4; i++) { v[i] = s; s += g_indeg[base + i]; }
    ssum[t] = s; __syncthreads();
    for (int off = 1; off < 1024; off <<= 1) {
        int x = (t >= off) ? ssum[t - off] : 0;
        __syncthreads();
        ssum[t] += x;
        __syncthreads();
    }
    int pre = (t == 0) ? 0 : ssum[t - 1];
#pragma unroll
    for (int i = 0; i < 4; i++) g_cscPtr[base + i] = pre + v[i];
    if (t == 1023) g_cscPtr[BN] = ssum[1023];
}

__global__ void k_cscfill() {
    int warp = blockIdx.x * (blockDim.x >> 5) + (threadIdx.x >> 5);
    int lane = threadIdx.x & 31;
    if (warp >= BN) return;
    int b = warp / NN;
    int rbase = g_rowptr[warp];
    int deg = g_deg[warp];
    for (int idx = lane; idx < deg; idx += 32) {
        int dst = b*NN + g_col[rbase + idx];
        int pos = g_cscPtr[dst] + atomicAdd(&g_cscFill[dst], 1);
        g_cscSrc[pos] = warp;
        g_cscEdge[pos] = rbase + idx;
    }
}

// z = h @ attn_W per head; s_src/s_dst row scores. block (128 thr) per node.
__global__ void k_z(const float* __restrict__ attn_W, const float* __restrict__ a_src,
                    const float* __restrict__ a_dst) {
    int node = blockIdx.x;
    int t = threadIdx.x;
    int head = t >> 6, e = t & 63;
    __shared__ float hs[EE];
    __shared__ float rs[2], rd[2];
    if (t < EE) hs[t] = g_h[node*EE + t];
    if (t < 2) { rs[t] = 0.f; rd[t] = 0.f; }
    __syncthreads();
    const float* W = attn_W + head*EE*EE;
    float a0 = 0.f, a1 = 0.f, a2 = 0.f, a3 = 0.f;
#pragma unroll 4
    for (int d = 0; d < EE; d += 4) {
        a0 = fmaf(hs[d],     W[d*EE + e],       a0);
        a1 = fmaf(hs[d + 1], W[(d + 1)*EE + e], a1);
        a2 = fmaf(hs[d + 2], W[(d + 2)*EE + e], a2);
        a3 = fmaf(hs[d + 3], W[(d + 3)*EE + e], a3);
    }
    float acc = (a0 + a1) + (a2 + a3);
    size_t zi = ((size_t)head*BN + node)*EE + e;
    g_z[zi] = acc;
    g_zb[zi] = __float2bfloat16(acc);
    float vs = acc * a_src[head*EE + e];
    float vd = acc * a_dst[head*EE + e];
#pragma unroll
    for (int o = 16; o > 0; o >>= 1) {
        vs += __shfl_xor_sync(0xffffffffu, vs, o);
        vd += __shfl_xor_sync(0xffffffffu, vd, o);
    }
    if ((t & 31) == 0) { atomicAdd(&rs[head], vs); atomicAdd(&rd[head], vd); }
    __syncthreads();
    if (t < 2) { g_ssrc[t*BN + node] = rs[t]; g_sdst[t*BN + node] = rd[t]; }
}

// column means of z (fallback for degree-0 rows). grid = HH*BB*16, block 64.
__global__ void k_zmean_acc() {
    int hb = blockIdx.x >> 4;
    int c = blockIdx.x & 15;
    int e = threadIdx.x;
    float acc = 0.f;
    for (int n = c*128; n < c*128 + 128; n++)
        acc += g_z[((size_t)hb*NN + n)*EE + e];
    atomicAdd(&g_zmean[hb*EE + e], acc * (1.0f / NN));
}

// sparse attention aggregation: one warp per (head,k,node). bf16x2 gathers, fp32 accumulate.
__global__ void k_agg() {
    int warp = blockIdx.x * (blockDim.x >> 5) + (threadIdx.x >> 5);
    int lane = threadIdx.x & 31;
    if (warp >= HH*KK*BN) return;
    int head = warp / (KK*BN);
    int rem = warp - head*(KK*BN);
    int k = rem / BN;
    int node = rem - k*BN;
    int b = node / NN;
    float ss = g_ssrc[head*BN + node];
    const float* sd = g_sdst + head*BN + b*NN;
    const __nv_bfloat162* z =
        reinterpret_cast<const __nv_bfloat162*>(g_zb + ((size_t)head*BN + (size_t)b*NN)*EE);
    int crow = k*BN + node;
    int rbase = g_rowptr[crow];
    int deg = g_deg[crow];
    float accx = 0.f, accy = 0.f, Z = 0.f;
    for (int i0 = 0; i0 < deg; i0 += 32) {
        int idx = i0 + lane;
        int m = (idx < deg) ? __ldg(&g_col[rbase + idx]) : -1;
        float w = (m >= 0) ? expf(tanhf(ss + sd[m])) : 0.f;
        float r = w;
#pragma unroll
        for (int o = 16; o > 0; o >>= 1) r += __shfl_xor_sync(0xffffffffu, r, o);
        Z += r;
        int cnt = deg - i0; if (cnt > 32) cnt = 32;
#pragma unroll 4
        for (int j = 0; j < cnt; j++) {
            int   mj = __shfl_sync(0xffffffffu, m, j);
            float wj = __shfl_sync(0xffffffffu, w, j);
            float2 v = __bfloat1622float2(__ldg(&z[mj*32 + lane]));
            accx = fmaf(wj, v.x, accx);
            accy = fmaf(wj, v.y, accy);
        }
    }
    float2 outv;
    if (deg > 0) {
        float inv = 1.f / Z;
        outv.x = accx * inv; outv.y = accy * inv;
    } else {
        outv.x = g_zmean[(head*BB + b)*EE + 2*lane];
        outv.y = g_zmean[(head*BB + b)*EE + 2*lane + 1];
    }
    float2* dst = (float2*)(g_aggp + (((size_t)head*BN + node)*KK + k)*EE);
    dst[lane] = outv;
}

// combine heads + neighborhood attention over k + GRU update. block (64 thr) per node.
// also re-zeroes g_zmean (block 0) for the next layer.
__global__ void k_update(const float* __restrict__ nbr_q, const float* __restrict__ gru_W,
                         const float* __restrict__ gru_U, const float* __restrict__ gru_b) {
    int node = blockIdx.x;
    int e = threadIdx.x;
    __shared__ float a0[EE], a1[EE], hs[EE], nxt[EE], rh[EE];
    __shared__ float red[2];
    size_t i00 = (((size_t)0*BN + node)*KK + 0)*EE + e;
    size_t i01 = (((size_t)0*BN + node)*KK + 1)*EE + e;
    size_t i10 = (((size_t)1*BN + node)*KK + 0)*EE + e;
    size_t i11 = (((size_t)1*BN + node)*KK + 1)*EE + e;
    a0[e] = tanhf(0.5f*(g_aggp[i00] + g_aggp[i10]));
    a1[e] = tanhf(0.5f*(g_aggp[i01] + g_aggp[i11]));
    hs[e] = g_h[node*EE + e];
    if (e < 2) red[e] = 0.f;
    if (node == 0) {
        g_zmean[e] = 0.f; g_zmean[64 + e] = 0.f;
        g_zmean[128 + e] = 0.f; g_zmean[192 + e] = 0.f;
    }
    __syncthreads();
    float q = nbr_q[e];
    float v0 = a0[e]*q, v1 = a1[e]*q;
#pragma unroll
    for (int o = 16; o > 0; o >>= 1) {
        v0 += __shfl_xor_sync(0xffffffffu, v0, o);
        v1 += __shfl_xor_sync(0xffffffffu, v1, o);
    }
    if ((e & 31) == 0) { atomicAdd(&red[0], v0); atomicAdd(&red[1], v1); }
    __syncthreads();
    float t0 = tanhf(red[0]), t1 = tanhf(red[1]);
    float e0 = expf(t0), e1 = expf(t1);
    float inv = 1.f / (e0 + e1);
    nxt[e] = e0*inv*a0[e] + e1*inv*a1[e];
    __syncthreads();
    float sW0 = 0.f, sW1 = 0.f, sW2 = 0.f, sU0 = 0.f, sU1 = 0.f;
#pragma unroll 8
    for (int d = 0; d < EE; d++) {
        float nd = nxt[d], hd = hs[d];
        const float* Wr = gru_W + d*192;
        const float* Ur = gru_U + d*192;
        sW0 = fmaf(nd, Wr[e],       sW0);
        sW1 = fmaf(nd, Wr[e + 64],  sW1);
        sW2 = fmaf(nd, Wr[e + 128], sW2);
        sU0 = fmaf(hd, Ur[e],       sU0);
        sU1 = fmaf(hd, Ur[e + 64],  sU1);
    }
    float zg = 1.f / (1.f + expf(-(sW0 + sU0 + gru_b[e])));
    float r  = 1.f / (1.f + expf(-(sW1 + sU1 + gru_b[e + 64])));
    rh[e] = r * hs[e];
    __syncthreads();
    float sU2 = 0.f;
#pragma unroll 8
    for (int d = 0; d < EE; d++) sU2 = fmaf(rh[d], gru_U[d*192 + e + 128], sU2);
    float htl = tanhf(sW2 + sU2 + gru_b[e + 128]);
    g_h[node*EE + e] = (1.f - zg)*hs[e] + zg*htl;
}

// decoder + dual-var MLPs fused. block (64 thr) per node.
__global__ void k_decode(const float* __restrict__ dW0, const float* __restrict__ db0,
                         const float* __restrict__ dW1, const float* __restrict__ db1,
                         const float* __restrict__ uW0, const float* __restrict__ ub0,
                         const float* __restrict__ uW1, const float* __restrict__ ub1) {
    int node = blockIdx.x;
    int e = threadIdx.x;
    __shared__ float hs[EE];
    __shared__ float red[2];
    hs[e] = g_h[node*EE + e];
    if (e < 2) red[e] = 0.f;
    __syncthreads();
    float ad = db0[e], au = ub0[e];
#pragma unroll 8
    for (int d = 0; d < EE; d++) {
        float hd = hs[d];
        ad = fmaf(hd, dW0[d*64 + e], ad);
        au = fmaf(hd, uW0[d*64 + e], au);
    }
    float vd = tanhf(ad) * dW1[e];
    float vu = tanhf(au) * uW1[e];
#pragma unroll
    for (int o = 16; o > 0; o >>= 1) {
        vd += __shfl_xor_sync(0xffffffffu, vd, o);
        vu += __shfl_xor_sync(0xffffffffu, vu, o);
    }
    if ((e & 31) == 0) { atomicAdd(&red[0], vd); atomicAdd(&red[1], vu); }
    __syncthreads();
    if (e == 0) { g_nw[node] = red[0] + db1[0]; g_dv[node] = red[1] + ub1[0]; }
}

// per-edge prop (row softmax over neighbors). one warp per row.
__global__ void k_eprop() {
    int warp = blockIdx.x * (blockDim.x >> 5) + (threadIdx.x >> 5);
    int lane = threadIdx.x & 31;
    if (warp >= BN) return;
    int b = warp / NN;
    const float* nwb = g_nw + b*NN;
    int rbase = g_rowptr[warp];
    int deg = g_deg[warp];
    if (deg == 0) return;   // uniform row handled via g_deg flag downstream
    float mx = -3.0e38f;
    for (int idx = lane; idx < deg; idx += 32) mx = fmaxf(mx, nwb[g_col[rbase + idx]]);
#pragma unroll
    for (int o = 16; o > 0; o >>= 1) mx = fmaxf(mx, __shfl_xor_sync(0xffffffffu, mx, o));
    float sm = 0.f;
    for (int idx = lane; idx < deg; idx += 32) sm += expf(nwb[g_col[rbase + idx]] - mx);
#pragma unroll
    for (int o = 16; o > 0; o >>= 1) sm += __shfl_xor_sync(0xffffffffu, sm, o);
    float inv = 1.f / sm;
    for (int idx = lane; idx < deg; idx += 32)
        g_eprop[rbase + idx] = expf(nwb[g_col[rbase + idx]] - mx) * inv;
}

// s0 = relu(-d); seed uniform-mass scalar for iteration 0 inputs
__global__ void k_sinit(const float* __restrict__ demands) {
    int i = blockIdx.x * blockDim.x + threadIdx.x;
    if (i < BN) {
        float v = fmaxf(-demands[i], 0.f);
        g_s0[i] = v;
        if (g_deg[i] == 0 && v != 0.f) atomicAdd(&g_emptyArr[i / NN], v);
    }
}

// sparse matvec: s'_d = relu(sum_in p_e * s_src + emptyMass/N - d). warp per dst node.
__global__ void k_matvec(int it, const float* __restrict__ demands) {
    int warp = blockIdx.x * (blockDim.x >> 5) + (threadIdx.x >> 5);
    int lane = threadIdx.x & 31;
    if (warp >= BN) return;
    const float* sin  = (it & 1) ? g_s1 : g_s0;
    float*       sout = (it & 1) ? g_s0 : g_s1;
    int p0 = g_cscPtr[warp], p1 = g_cscPtr[warp + 1];
    float acc = 0.f;
    for (int q = p0 + lane; q < p1; q += 32)
        acc += g_eprop[g_cscEdge[q]] * sin[g_cscSrc[q]];
#pragma unroll
    for (int o = 16; o > 0; o >>= 1) acc += __shfl_xor_sync(0xffffffffu, acc, o);
    if (lane == 0) {
        int b = warp / NN;
        float uni = g_emptyArr[it*BB + b] * (1.0f / NN);
        float sv = fmaxf(acc + uni - demands[warp], 0.f);
        sout[warp] = sv;
        if (g_deg[warp] == 0 && sv != 0.f) atomicAdd(&g_emptyArr[(it + 1)*BB + b], sv);
    }
}

// fused sparse flow-cost + dual-edge-cost. warp per row over out-edges.
__global__ void k_cost() {
    int warp = blockIdx.x * (blockDim.x >> 5) + (threadIdx.x >> 5);
    int lane = threadIdx.x & 31;
    if (warp >= BN) return;
    int b = warp / NN;
    int rbase = g_rowptr[warp];
    int deg = g_deg[warp];
    const float* sfin = g_s1;   // after 9 matvecs, final s is in g_s1
    float si = sfin[warp];
    float dvi = g_dv[warp];
    float facc = 0.f, dacc = 0.f;
    for (int idx = lane; idx < deg; idx += 32) {
        int e = rbase + idx;
        int jg = b*NN + g_col[e];
        float f = g_eprop[e] * si;
        int r = g_erecip[e];
        float frec = (r >= 0) ? g_eprop[r] * sfin[jg]
                              : ((g_deg[jg] == 0) ? sfin[jg] * (1.0f / NN) : 0.f);
        float fl = f - fminf(f, frec);
        facc = fmaf(fl, fl, facc);
        float dd = dvi - g_dv[jg];
        float y = 0.f, m = 0.f;
#pragma unroll
        for (int itr = 0; itr < 10; itr++) {
            float g = 2.f*y - dd;
            m = 0.9f*m + g;
            y = fmaxf(y - 0.1f*m, 0.f);
        }
        dacc += y*y - dd*y;
    }
#pragma unroll
    for (int o = 16; o > 0; o >>= 1) {
        facc += __shfl_xor_sync(0xffffffffu, facc, o);
        dacc += __shfl_xor_sync(0xffffffffu, dacc, o);
    }
    if (lane == 0) {
        if (deg == 0) facc += si * si * (1.0f / NN);  // dense uniform row: sum_j (s_i/N)^2
        atomicAdd(&g_accflow[b], (double)facc);
        atomicAdd(&g_accdual[b], (double)dacc);
    }
}

// dual_demand + final combine: out[b] = flow_cost - (dual_edge - dual_demand)
__global__ void k_final(const float* __restrict__ demands, float* __restrict__ out) {
    int b = blockIdx.x;
    int t = threadIdx.x;
    double acc = 0.0;
    for (int n = t; n < NN; n += 256)
        acc += (double)(g_dv[b*NN + n] * demands[b*NN + n]);
    __shared__ double sred[256];
    sred[t] = acc; __syncthreads();
    for (int o = 128; o > 0; o >>= 1) { if (t < o) sred[t] += sred[t + o]; __syncthreads(); }
    if (t == 0) {
        double dual_cost = g_accdual[b] - sred[0];
        out[b] = (float)(g_accflow[b] - dual_cost);
    }
}

// ---------------------------------------------------------------------------------------
extern "C" void kernel_launch(void* const* d_in, const int* in_sizes, int n_in,
                              void* d_out, int out_size) {
    const float* node_features   = (const float*)d_in[0];
    const float* node_embeddings = (const float*)d_in[1];
    const float* demands = (const float*)d_in[2];
    const float* nbh     = (const float*)d_in[4];
    const float* enc_W0  = (const float*)d_in[5];
    const float* enc_b0  = (const float*)d_in[6];
    const float* enc_W1  = (const float*)d_in[7];
    const float* enc_b1  = (const float*)d_in[8];
    const float* attn_W  = (const float*)d_in[9];
    const float* a_src   = (const float*)d_in[10];
    const float* a_dst   = (const float*)d_in[11];
    const float* nbr_q   = (const float*)d_in[12];
    const float* gru_W   = (const float*)d_in[13];
    const float* gru_U   = (const float*)d_in[14];
    const float* gru_b   = (const float*)d_in[15];
    const float* dec_W0  = (const float*)d_in[16];
    const float* dec_b0  = (const float*)d_in[17];
    const float* dec_W1  = (const float*)d_in[18];
    const float* dec_b1  = (const float*)d_in[19];
    const float* dual_W0 = (const float*)d_in[20];
    const float* dual_b0 = (const float*)d_in[21];
    const float* dual_W1 = (const float*)d_in[22];
    const float* dual_b1 = (const float*)d_in[23];
    float* out = (float*)d_out;

    k_init<<<(BN + 255)/256, 256>>>();
    k_encoder<<<BN, 64>>>(node_embeddings, node_features, enc_W0, enc_b0, enc_W1, enc_b1);
    k_build_csr<<<(KK*BN)/8, 256>>>(nbh);
    k_recip_indeg<<<BN/8, 256>>>();
    k_scan<<<1, 1024>>>();
    k_cscfill<<<BN/8, 256>>>();

    for (int layer = 0; layer < 2; layer++) {
        k_z<<<BN, 128>>>(attn_W, a_src, a_dst);
        k_zmean_acc<<<HH*BB*16, 64>>>();
        k_agg<<<(HH*KK*BN)/8, 256>>>();
        k_update<<<BN, 64>>>(nbr_q, gru_W, gru_U, gru_b);
    }

    k_decode<<<BN, 64>>>(dec_W0, dec_b0, dec_W1, dec_b1, dual_W0, dual_b0, dual_W1, dual_b1);
    k_eprop<<<BN/8, 256>>>();
    k_sinit<<<(BN + 255)/256, 256>>>(demands);
    for (int it = 0; it < 9; it++)
        k_matvec<<<BN/8, 256>>>(it, demands);
    k_cost<<<BN/8, 256>>>();
    k_final<<<BB, 256>>>(demands, out);
}